// round 7
// baseline (speedup 1.0000x reference)
#include <cuda_runtime.h>
#include <cuda_fp16.h>
#include <cstdint>

#define S_LEN   8192
#define THREADS 256
#define CHUNK   (S_LEN / THREADS)   // 32
#define BIGI    (1 << 20)
#define B_MAX   512

__device__ float g_sum[B_MAX];
__device__ float g_cnt[B_MAX];

__device__ __forceinline__ int skew(int i) { return i + (i >> 5); }

__global__ void __launch_bounds__(THREADS)
loss_main(const float4* __restrict__ logits, const int* __restrict__ labels) {
    const int row = blockIdx.x;
    const int tid = threadIdx.x;
    const float4* lrow   = logits + (size_t)row * S_LEN;
    const int*    labrow = labels + (size_t)row * S_LEN;

    __shared__ __half   s_ce[S_LEN + S_LEN / 32];   // skewed: conflict-free strided reads
    __shared__ uint32_t s_plw[S_LEN / 4];           // packed pred/lab/valid bytes
    __shared__ int      sc[10][THREADS];            // block scan workspace
    unsigned char* s_pl = (unsigned char*)s_plw;

    // ---------------- Phase 0: coalesced load + pointwise compute ----------------
#pragma unroll 4
    for (int i = tid; i < S_LEN; i += THREADS) {
        float4 v   = lrow[i];
        int    lab = labrow[i];
        // first-occurrence argmax (matches jnp.argmax)
        int pred = 0; float m = v.x;
        if (v.y > m) { m = v.y; pred = 1; }
        if (v.z > m) { m = v.z; pred = 2; }
        if (v.w > m) { m = v.w; pred = 3; }
        bool valid = (lab != -100);
        int  lb    = valid ? lab : 0;
        float ce = 0.0f;
        if (valid) {
            float e   = __expf(v.x - m) + __expf(v.y - m) + __expf(v.z - m) + __expf(v.w - m);
            float lse = m + __logf(e);
            float xl  = (lb == 0) ? v.x : (lb == 1) ? v.y : (lb == 2) ? v.z : v.w;
            float w   = (lb >= 2) ? 30.0f : 1.0f;
            ce = (lse - xl) * w;
        }
        s_ce[skew(i)] = __float2half(ce);
        s_pl[i] = (unsigned char)(pred | (lb << 2) | (valid ? 16 : 0));
    }
    __syncthreads();

    // ---------------- Phase 1: per-thread chunk summaries ----------------
    const int base = tid * CHUNK;
    uint32_t plw[CHUNK / 4];
#pragma unroll
    for (int j = 0; j < CHUNK / 4; j++) plw[j] = s_plw[tid * (CHUNK / 4) + j];

    int encP = -1, encL = -1;   // (idx<<1)|bit of last VALID pred/lab mode in chunk
    int tLast2 = -1, tLast3 = -1, pLast2 = -1, pLast3 = -1;
    int tFirst2 = BIGI, tFirst3 = BIGI, pFirst2 = BIGI, pFirst3 = BIGI;
#pragma unroll
    for (int t = 0; t < CHUNK; t++) {
        unsigned pb = (plw[t >> 2] >> ((t & 3) * 8)) & 0xffu;
        int pred = pb & 3, lb = (pb >> 2) & 3;
        bool valid = (pb & 16) != 0;
        int g = base + t;
        if (valid) { encP = (g << 1) | (pred & 1); encL = (g << 1) | (lb & 1); }
        if (lb == 2)   { tLast2 = g; if (tFirst2 == BIGI) tFirst2 = g; }
        if (lb == 3)   { tLast3 = g; if (tFirst3 == BIGI) tFirst3 = g; }
        if (pred == 2) { pLast2 = g; if (pFirst2 == BIGI) pFirst2 = g; }
        if (pred == 3) { pLast3 = g; if (pFirst3 == BIGI) pFirst3 = g; }
    }

    // ---------------- Phase 2: 10 fused Hillis-Steele block scans ----------------
    sc[0][tid] = encP;    sc[1][tid] = encL;
    sc[2][tid] = tLast2;  sc[3][tid] = tLast3;  sc[4][tid] = pLast2;  sc[5][tid] = pLast3;
    sc[6][tid] = tFirst2; sc[7][tid] = tFirst3; sc[8][tid] = pFirst2; sc[9][tid] = pFirst3;
    __syncthreads();
    for (int d = 1; d < THREADS; d <<= 1) {
        int up0 = 0, up1 = 0, up2 = 0, up3 = 0, up4 = 0, up5 = 0;
        int dn0 = 0, dn1 = 0, dn2 = 0, dn3 = 0;
        bool hu = (tid >= d), hd = (tid + d < THREADS);
        if (hu) {
            up0 = sc[0][tid - d]; up1 = sc[1][tid - d]; up2 = sc[2][tid - d];
            up3 = sc[3][tid - d]; up4 = sc[4][tid - d]; up5 = sc[5][tid - d];
        }
        if (hd) {
            dn0 = sc[6][tid + d]; dn1 = sc[7][tid + d];
            dn2 = sc[8][tid + d]; dn3 = sc[9][tid + d];
        }
        __syncthreads();
        if (hu) {
            sc[0][tid] = max(sc[0][tid], up0); sc[1][tid] = max(sc[1][tid], up1);
            sc[2][tid] = max(sc[2][tid], up2); sc[3][tid] = max(sc[3][tid], up3);
            sc[4][tid] = max(sc[4][tid], up4); sc[5][tid] = max(sc[5][tid], up5);
        }
        if (hd) {
            sc[6][tid] = min(sc[6][tid], dn0); sc[7][tid] = min(sc[7][tid], dn1);
            sc[8][tid] = min(sc[8][tid], dn2); sc[9][tid] = min(sc[9][tid], dn3);
        }
        __syncthreads();
    }
    // exclusive prefix values + row totals
    int epm = tid ? sc[0][tid - 1] : -1;
    int etm = tid ? sc[1][tid - 1] : -1;
    int lT2 = tid ? sc[2][tid - 1] : -1;  if (lT2 < 0) lT2 = -BIGI;
    int lT3 = tid ? sc[3][tid - 1] : -1;  if (lT3 < 0) lT3 = -BIGI;
    int lP2 = tid ? sc[4][tid - 1] : -1;  if (lP2 < 0) lP2 = -BIGI;
    int lP3 = tid ? sc[5][tid - 1] : -1;  if (lP3 < 0) lP3 = -BIGI;
    bool hasT2 = sc[2][THREADS - 1] >= 0;
    bool hasT3 = sc[3][THREADS - 1] >= 0;
    bool hasP2 = sc[4][THREADS - 1] >= 0;
    bool hasP3 = sc[5][THREADS - 1] >= 0;
    int nT2 = (tid < THREADS - 1) ? sc[6][tid + 1] : BIGI;
    int nT3 = (tid < THREADS - 1) ? sc[7][tid + 1] : BIGI;
    int nP2 = (tid < THREADS - 1) ? sc[8][tid + 1] : BIGI;
    int nP3 = (tid < THREADS - 1) ? sc[9][tid + 1] : BIGI;

    // ------------ Phase 3a: backward walk (bwd distances, 4x4 bits/pos) ------------
    uint32_t bw[CHUNK / 2];
#pragma unroll
    for (int t = CHUNK - 1; t >= 0; t--) {
        unsigned pb = (plw[t >> 2] >> ((t & 3) * 8)) & 0xffu;
        int pred = pb & 3, lb = (pb >> 2) & 3;
        int g = base + t;
        if (lb == 2)   nT2 = g;
        if (lb == 3)   nT3 = g;
        if (pred == 2) nP2 = g;
        if (pred == 3) nP3 = g;
        unsigned dT2 = min(nT2 - g, 15), dT3 = min(nT3 - g, 15);
        unsigned dP2 = min(nP2 - g, 15), dP3 = min(nP3 - g, 15);
        unsigned pack = dT2 | (dT3 << 4) | (dP2 << 8) | (dP3 << 12);
        if (t & 1) bw[t >> 1]  = pack << 16;
        else       bw[t >> 1] |= pack;
    }

    // ------------ Phase 3b: forward walk (state machine + multipliers) ------------
    int pm = (epm < 0) ? 0 : (epm & 1);
    int tm = (etm < 0) ? 0 : (etm & 1);
    float acc = 0.0f;
    int   cnt = 0;
#pragma unroll
    for (int t = 0; t < CHUNK; t++) {
        unsigned pb = (plw[t >> 2] >> ((t & 3) * 8)) & 0xffu;
        int pred = pb & 3, lb = (pb >> 2) & 3;
        bool valid = (pb & 16) != 0;
        int g = base + t;
        float mult = 1.0f;
        if (valid) {
            if ((pred == 2 && pm == 0) || (pred == 3 && pm == 1)) mult = 100.0f;  // INV_PEN
            if ((lb == 2 && tm == 1 && pred == 2) ||
                (lb == 3 && tm == 0 && pred == 3)) mult *= 0.1f;                  // bonus
        }
        // update last-occurrence-at-or-before (dist 0 at own position)
        if (lb == 2)   lT2 = g;
        if (lb == 3)   lT3 = g;
        if (pred == 2) lP2 = g;
        if (pred == 3) lP3 = g;
        unsigned pk = (bw[t >> 1] >> ((t & 1) * 16)) & 0xffffu;
        if (pred == 2) {
            int d = min(g - lT2, (int)(pk & 15));
            float mp = hasT2 ? ((d == 0) ? 0.1f
                       : (d <= 5) ? ((d == 1) ? 0.7f : (d == 2) ? 0.49f : (d == 3) ? 0.343f
                                    : (d == 4) ? 0.2401f : 0.16807f)
                       : 10.0f) : 20.0f;
            mult *= mp;
        }
        if (pred == 3) {
            int d = min(g - lT3, (int)((pk >> 4) & 15));
            float mp = hasT3 ? ((d == 0) ? 0.1f
                       : (d <= 5) ? ((d == 1) ? 0.7f : (d == 2) ? 0.49f : (d == 3) ? 0.343f
                                    : (d == 4) ? 0.2401f : 0.16807f)
                       : 10.0f) : 20.0f;
            mult *= mp;
        }
        if (lb == 2) {  // lb==2 implies valid (labels==2)
            int d = min(g - lP2, (int)((pk >> 8) & 15));
            mult *= hasP2 ? ((d > 5) ? 2.0f : 1.0f) : 3.0f;
        }
        if (lb == 3) {
            int d = min(g - lP3, (int)((pk >> 12) & 15));
            mult *= hasP3 ? ((d > 5) ? 2.0f : 1.0f) : 3.0f;
        }
        if (valid) {
            acc += __half2float(s_ce[skew(g)]) * mult;
            cnt++;
            pm = pred & 1;
            tm = lb & 1;
        }
    }

    // ---------------- Block reduction (deterministic) ----------------
    __syncthreads();  // everyone done reading sc / s_plw before reuse
    float* rsum = (float*)s_plw;
    float* rcnt = (float*)&sc[0][0];
    rsum[tid] = acc;
    rcnt[tid] = (float)cnt;
    __syncthreads();
    for (int d = THREADS / 2; d > 0; d >>= 1) {
        if (tid < d) { rsum[tid] += rsum[tid + d]; rcnt[tid] += rcnt[tid + d]; }
        __syncthreads();
    }
    if (tid == 0) { g_sum[row] = rsum[0]; g_cnt[row] = rcnt[0]; }
}

__global__ void __launch_bounds__(512)
loss_finish(float* __restrict__ out, int Bn) {
    __shared__ float ss[512], sct[512];
    int tid = threadIdx.x;
    ss[tid]  = (tid < Bn) ? g_sum[tid] : 0.0f;
    sct[tid] = (tid < Bn) ? g_cnt[tid] : 0.0f;
    __syncthreads();
    for (int d = 256; d > 0; d >>= 1) {
        if (tid < d) { ss[tid] += ss[tid + d]; sct[tid] += sct[tid + d]; }
        __syncthreads();
    }
    if (tid == 0) out[0] = ss[0] / fmaxf(sct[0], 1.0f);
}

extern "C" void kernel_launch(void* const* d_in, const int* in_sizes, int n_in,
                              void* d_out, int out_size) {
    const float* logits = (const float*)d_in[0];
    const int*   labels = (const int*)d_in[1];
    int Bn = in_sizes[1] / S_LEN;
    if (Bn > B_MAX) Bn = B_MAX;
    loss_main<<<Bn, THREADS>>>((const float4*)logits, labels);
    loss_finish<<<1, 512>>>((float*)d_out, Bn);
}